// round 14
// baseline (speedup 1.0000x reference)
#include <cuda_runtime.h>
#include <cuda_fp16.h>
#include <math.h>
#include <stdint.h>

#define BB 4
#define QQ 10000
#define EE 256
#define NHH 8
#define S_TOTAL 19560

__constant__ int c_HL[4] = {92, 46, 23, 12};
__constant__ int c_WL[4] = {160, 80, 40, 20};
__constant__ int c_ST[4] = {0, 14720, 18400, 19320};

// Scratch (no cudaMalloc allowed)
__device__ __half g_vdup[BB * NHH * S_TOTAL * 64]; // pixel pairs {v[p], v[p+1]}, 128B each
__device__ float g_oa[BB * QQ * 768];              // [off(512) | attn(256)] per (b,q)
__device__ __half g_wth[262144];                   // weights fp16 [n][k]: val(256) | off+attn(768)

__device__ __forceinline__ uint32_t smem_u32(const void* p) {
    uint32_t a;
    asm("{ .reg .u64 t; cvta.to.shared.u64 t, %1; cvt.u32.u64 %0, t; }" : "=r"(a) : "l"(p));
    return a;
}

#define LDMATRIX_X4(r, addr) \
    asm volatile("ldmatrix.sync.aligned.m8n8.x4.shared.b16 {%0,%1,%2,%3}, [%4];" \
        : "=r"((r)[0]), "=r"((r)[1]), "=r"((r)[2]), "=r"((r)[3]) : "r"(addr))

#define MMA_F16(d, a, b) \
    asm volatile("mma.sync.aligned.m16n8k16.row.col.f32.f16.f16.f32 " \
        "{%0,%1,%2,%3}, {%4,%5,%6,%7}, {%8,%9}, {%0,%1,%2,%3};" \
        : "+f"((d)[0]), "+f"((d)[1]), "+f"((d)[2]), "+f"((d)[3]) \
        : "r"((a)[0]), "r"((a)[1]), "r"((a)[2]), "r"((a)[3]), "r"((b)[0]), "r"((b)[1]))

// ------------------------- weight prep (tiny) --------------------------------
__global__ __launch_bounds__(256) void wprep_kernel(
    const float* __restrict__ w_val, const float* __restrict__ w_off,
    const float* __restrict__ w_att, __half* __restrict__ th)
{
    int idx = blockIdx.x * 256 + threadIdx.x;
    float v;
    if (idx < 65536) {
        int n = idx >> 8, k = idx & 255;
        v = w_val[k * 256 + n];
    } else {
        int j = idx - 65536;
        int n = j >> 8, k = j & 255;
        v = (n < 512) ? w_off[k * 512 + n] : w_att[k * 256 + (n - 512)];
    }
    th[idx] = __float2half_rn(v);
}

// ------------------------- merged fused-convert fp16 GEMM --------------------
// One launch: blocks [0,1878) = query GEMM (N=768, mode 0),
//             blocks [1878,3102) = value GEMM (N=256, mode 1, dual-write pairs).

#define A32_STRIDE 144
#define A32_TILE   (128 * A32_STRIDE)
#define A16_STRIDE 80
#define A16_TILE   (128 * A16_STRIDE)
#define B_TILE     10240
#define OFF_A16    (2 * A32_TILE)
#define OFF_B      (OFF_A16 + A16_TILE)
#define SMEM_TOTAL (OFF_B + 3 * B_TILE)

#define NQ_TILES 1878    // 6 x 313
#define NV_TILES 1224    // 2 x 612

__device__ __forceinline__ int bdiv_s(int m) {
    return (m >= 2 * S_TOTAL) ? (m >= 3 * S_TOTAL ? 3 : 2) : (m >= S_TOTAL ? 1 : 0);
}

__device__ __forceinline__ void load_stage(
    uint32_t sbase, int a_stage, int b_stage,
    const char* A, const char* Bm, int bm, int bn, int M, int c, int tid)
{
    const uint32_t adst0 = sbase + a_stage * A32_TILE;
#pragma unroll
    for (int it = 0; it < 4; it++) {
        int idx = tid + it * 256;
        int row = idx >> 3;
        int g = (idx & 7) << 4;
        uint32_t dst = adst0 + row * A32_STRIDE + g;
        const char* src = A + (size_t)(bm + row) * 1024 + c * 128 + g;
        int ssize = (bm + row < M) ? 16 : 0;
        asm volatile("cp.async.ca.shared.global [%0], [%1], 16, %2;"
                     :: "r"(dst), "l"(src), "r"(ssize) : "memory");
    }
    const uint32_t bdst0 = sbase + OFF_B + b_stage * B_TILE;
#pragma unroll
    for (int it = 0; it < 2; it++) {
        int idx = tid + it * 256;
        int row = idx >> 2;
        int g = (idx & 3) << 4;
        uint32_t dst = bdst0 + row * A16_STRIDE + g;
        const char* src = Bm + (size_t)(bn + row) * 512 + c * 64 + g;
        asm volatile("cp.async.ca.shared.global [%0], [%1], 16, 16;"
                     :: "r"(dst), "l"(src) : "memory");
    }
}

__global__ __launch_bounds__(256, 2) void gemm_merged(
    const float* __restrict__ query, const float* __restrict__ value,
    const __half* __restrict__ wth,
    const float* __restrict__ b_off, const float* __restrict__ b_att,
    const float* __restrict__ b_val, float* __restrict__ C)
{
    extern __shared__ char smem[];
    const uint32_t sbase = smem_u32(smem);
    const int tid = threadIdx.x;
    const int wid = tid >> 5, lane = tid & 31;
    const int warp_m = wid >> 2, warp_n = wid & 3;

    const float* A_g;
    const __half* B_g;
    const float *bias1, *bias2;
    int bsplit, M, N, mode, bm, bn;
    {
        const int bid = blockIdx.x;
        if (bid < NQ_TILES) {
            A_g = query; B_g = wth + 65536;
            bias1 = b_off; bias2 = b_att; bsplit = 512;
            M = BB * QQ; N = 768; mode = 0;
            bn = (bid % 6) * 128; bm = (bid / 6) * 128;
        } else {
            const int v = bid - NQ_TILES;
            A_g = value; B_g = wth;
            bias1 = b_val; bias2 = b_val; bsplit = 1 << 30;
            M = BB * S_TOTAL; N = 256; mode = 1;
            bn = (v % 2) * 128; bm = (v / 2) * 128;
        }
    }

    const char* Ac = reinterpret_cast<const char*>(A_g);
    const char* Bc = reinterpret_cast<const char*>(B_g);

    float acc[4][4][4];
#pragma unroll
    for (int mt = 0; mt < 4; mt++)
#pragma unroll
        for (int nt = 0; nt < 4; nt++)
#pragma unroll
            for (int r = 0; r < 4; r++) acc[mt][nt][r] = 0.f;

    load_stage(sbase, 0, 0, Ac, Bc, bm, bn, M, 0, tid);
    asm volatile("cp.async.commit_group;" ::: "memory");
    load_stage(sbase, 1, 1, Ac, Bc, bm, bn, M, 1, tid);
    asm volatile("cp.async.commit_group;" ::: "memory");

    const uint32_t a_row = warp_m * 64 + (lane & 15);
    const uint32_t a_off = (uint32_t)((lane >> 4) << 4);
    const uint32_t b_row = warp_n * 32 + (lane & 7) + ((lane >> 4) << 3);
    const uint32_t b_off2 = (uint32_t)(((lane >> 3) & 1) << 4);

    const int cv_row = tid >> 1;
    const int cv_sel = tid & 1;

    int b_rd = 0, b_wr = 2;
#pragma unroll 1
    for (int c = 0; c < 8; c++) {
        asm volatile("cp.async.wait_group 1;" ::: "memory");
        __syncthreads();

        // ---- convert A fp32 -> fp16 ----
        {
            const char* srcp = smem + (c & 1) * A32_TILE + cv_row * A32_STRIDE + cv_sel * 64;
            float4 f0 = *reinterpret_cast<const float4*>(srcp + 0);
            float4 f1 = *reinterpret_cast<const float4*>(srcp + 16);
            float4 f2 = *reinterpret_cast<const float4*>(srcp + 32);
            float4 f3 = *reinterpret_cast<const float4*>(srcp + 48);
            __half2 h0 = __floats2half2_rn(f0.x, f0.y), h1 = __floats2half2_rn(f0.z, f0.w);
            __half2 h2 = __floats2half2_rn(f1.x, f1.y), h3 = __floats2half2_rn(f1.z, f1.w);
            __half2 h4 = __floats2half2_rn(f2.x, f2.y), h5 = __floats2half2_rn(f2.z, f2.w);
            __half2 h6 = __floats2half2_rn(f3.x, f3.y), h7 = __floats2half2_rn(f3.z, f3.w);
            char* dstp = smem + OFF_A16 + cv_row * A16_STRIDE + cv_sel * 32;
            *reinterpret_cast<uint4*>(dstp) = make_uint4(
                *reinterpret_cast<uint32_t*>(&h0), *reinterpret_cast<uint32_t*>(&h1),
                *reinterpret_cast<uint32_t*>(&h2), *reinterpret_cast<uint32_t*>(&h3));
            *reinterpret_cast<uint4*>(dstp + 16) = make_uint4(
                *reinterpret_cast<uint32_t*>(&h4), *reinterpret_cast<uint32_t*>(&h5),
                *reinterpret_cast<uint32_t*>(&h6), *reinterpret_cast<uint32_t*>(&h7));
        }
        __syncthreads();

        if (c + 2 < 8)
            load_stage(sbase, c & 1, b_wr, Ac, Bc, bm, bn, M, c + 2, tid);
        asm volatile("cp.async.commit_group;" ::: "memory");

        const uint32_t sa = sbase + OFF_A16;
        const uint32_t sb = sbase + OFF_B + b_rd * B_TILE;
        uint32_t ah[4][4], bh[4][2];
#pragma unroll
        for (int mt = 0; mt < 4; mt++)
            LDMATRIX_X4(ah[mt], sa + (a_row + mt * 16) * A16_STRIDE + a_off);
#pragma unroll
        for (int g = 0; g < 2; g++) {
            uint32_t rh[4];
            LDMATRIX_X4(rh, sb + (b_row + g * 16) * A16_STRIDE + b_off2);
            bh[2 * g][0] = rh[0]; bh[2 * g][1] = rh[1];
            bh[2 * g + 1][0] = rh[2]; bh[2 * g + 1][1] = rh[3];
        }
#pragma unroll
        for (int mt = 0; mt < 4; mt++)
#pragma unroll
            for (int nt = 0; nt < 4; nt++)
                MMA_F16(acc[mt][nt], ah[mt], bh[nt]);

#pragma unroll
        for (int mt = 0; mt < 4; mt++)
            LDMATRIX_X4(ah[mt], sa + (a_row + mt * 16) * A16_STRIDE + 32 + a_off);
#pragma unroll
        for (int g = 0; g < 2; g++) {
            uint32_t rh[4];
            LDMATRIX_X4(rh, sb + (b_row + g * 16) * A16_STRIDE + 32 + b_off2);
            bh[2 * g][0] = rh[0]; bh[2 * g][1] = rh[1];
            bh[2 * g + 1][0] = rh[2]; bh[2 * g + 1][1] = rh[3];
        }
#pragma unroll
        for (int mt = 0; mt < 4; mt++)
#pragma unroll
            for (int nt = 0; nt < 4; nt++)
                MMA_F16(acc[mt][nt], ah[mt], bh[nt]);

        b_rd = (b_rd == 2) ? 0 : b_rd + 1;
        b_wr = (b_wr == 2) ? 0 : b_wr + 1;
    }

    const int q = lane >> 2, t = lane & 3;
    if (mode == 0) {
#pragma unroll
        for (int mt = 0; mt < 4; mt++) {
            int m0 = bm + warp_m * 64 + mt * 16 + q;
#pragma unroll
            for (int nt = 0; nt < 4; nt++) {
                int n = bn + warp_n * 32 + nt * 8 + 2 * t;
                float b0 = (n < bsplit) ? bias1[n] : bias2[n - bsplit];
                float b1 = (n + 1 < bsplit) ? bias1[n + 1] : bias2[n + 1 - bsplit];
                if (m0 < M)
                    *reinterpret_cast<float2*>(C + (size_t)m0 * N + n) =
                        make_float2(acc[mt][nt][0] + b0, acc[mt][nt][1] + b1);
                if (m0 + 8 < M)
                    *reinterpret_cast<float2*>(C + (size_t)(m0 + 8) * N + n) =
                        make_float2(acc[mt][nt][2] + b0, acc[mt][nt][3] + b1);
            }
        }
    } else {
        __half2* vf = reinterpret_cast<__half2*>(g_vdup);
#pragma unroll
        for (int mt = 0; mt < 4; mt++) {
            int m0 = bm + warp_m * 64 + mt * 16 + q;
#pragma unroll
            for (int nt = 0; nt < 4; nt++) {
                int n = bn + warp_n * 32 + nt * 8 + 2 * t;
                int h = n >> 5, d = n & 31;
                float b0 = bias1[n], b1 = bias1[n + 1];
#pragma unroll
                for (int rr = 0; rr < 2; rr++) {
                    int m = m0 + rr * 8;
                    if (m < M) {
                        int bb = bdiv_s(m);
                        int s = m - bb * S_TOTAL;
                        size_t ip = (size_t)(bb * 8 + h) * S_TOTAL + s;
                        __half2 hv = __floats2half2_rn(acc[mt][nt][2 * rr] + b0,
                                                       acc[mt][nt][2 * rr + 1] + b1);
                        vf[ip * 32 + (d >> 1)] = hv;
                        if (s > 0)
                            vf[(ip - 1) * 32 + 16 + (d >> 1)] = hv;
                    }
                }
            }
        }
    }
}

// ------------------------- fused softmax + sampling -------------------------
// Meta layout: entry E(midx, parity, it) = midx*32 + parity*16 + it  (8B each).
// Phase 2: lane = [half|midx|chunk]; per 2 iterations one LDS.128 fetches
//          {addr0,w0,addr1,w1}; 2 LDG.128 + 8 HFMA2. Group-of-4 flush to fp32.
__global__ __launch_bounds__(256, 8) void sample_kernel(
    const float* __restrict__ ref, float* __restrict__ out)
{
    __shared__ uint2 sMeta[8][128];

    const int w = threadIdx.x >> 5;
    const int lane = threadIdx.x & 31;
    const int warp_global = blockIdx.x * 8 + w;
    const int h = warp_global & 7;
    const int bq = warp_global >> 3;
    const int b = bq / QQ;

    float logit = g_oa[(size_t)bq * 768 + 512 + h * 32 + lane];
    float m = logit;
#pragma unroll
    for (int o = 16; o; o >>= 1) m = fmaxf(m, __shfl_xor_sync(0xFFFFFFFFu, m, o));
    float e = __expf(logit - m);
    float s = e;
#pragma unroll
    for (int o = 16; o; o >>= 1) s += __shfl_xor_sync(0xFFFFFFFFu, s, o);
    const float aw = e / s;

    const int l = lane >> 3;
    const int p = lane & 7;
    const int z = p & 3;
    const float2 off2 = *reinterpret_cast<const float2*>(g_oa + (size_t)bq * 768 + h * 64 + lane * 2);
    const float2 r2 = *reinterpret_cast<const float2*>(ref + ((size_t)bq * 4 + z) * 2);
    const int W = c_WL[l], H = c_HL[l], st = c_ST[l];
    const float px = r2.x * (float)W + off2.x - 0.5f;
    const float py = r2.y * (float)H + off2.y - 0.5f;
    const float x0f = floorf(px), y0f = floorf(py);
    const int x0 = (int)x0f, y0 = (int)y0f;
    const float fx = px - x0f, fy = py - y0f;
    const float gx = 1.f - fx, gy = 1.f - fy;
    const bool xi0 = (x0 >= 0) && (x0 < W);
    const bool yi0 = (y0 >= 0) && (y0 < H);
    const bool yi1 = (y0 >= -1) && (y0 < H - 1);
    const int bx = min(max(x0, 0), W - 1);
    const int yc0 = min(max(y0, 0), H - 1);
    const int yc1 = min(max(y0 + 1, 0), H - 1);

    const float wf = xi0 ? gx : ((x0 == -1) ? fx : 0.f);
    const float ws = (xi0 && (x0 + 1 < W)) ? fx : 0.f;
    const float wy0 = yi0 ? aw * gy : 0.f;
    const float wy1 = yi1 ? aw * fy : 0.f;

    const uint32_t basepix = (uint32_t)(b * 8 + h) * (uint32_t)S_TOTAL;
    const uint32_t aT = (basepix + (uint32_t)(st + yc0 * W + bx)) << 7;
    const uint32_t aB = (basepix + (uint32_t)(st + yc1 * W + bx)) << 7;
    {
        __half2 d0 = __half2half2(__float2half_rn(wy0 * wf));
        __half2 d1 = __half2half2(__float2half_rn(wy0 * ws));
        __half2 d2 = __half2half2(__float2half_rn(wy1 * wf));
        __half2 d3 = __half2half2(__float2half_rn(wy1 * ws));
        const int eb = (lane & 1) * 16 + (lane >> 1);   // parity*16 + it
        sMeta[w][0 * 32 + eb] = make_uint2(aT, *reinterpret_cast<uint32_t*>(&d0));
        sMeta[w][1 * 32 + eb] = make_uint2(aT, *reinterpret_cast<uint32_t*>(&d1));
        sMeta[w][2 * 32 + eb] = make_uint2(aB, *reinterpret_cast<uint32_t*>(&d2));
        sMeta[w][3 * 32 + eb] = make_uint2(aB, *reinterpret_cast<uint32_t*>(&d3));
    }
    __syncwarp();

    const int half = lane >> 4;
    const int midx = (lane >> 2) & 3;
    const uint32_t coff = (uint32_t)(lane & 7) * 16;
    const char* vbc = reinterpret_cast<const char*>(g_vdup) + coff;
    const uint2* mrow = &sMeta[w][midx * 32 + half * 16];

    float a0 = 0.f, a1 = 0.f, a2 = 0.f, a3 = 0.f, a4 = 0.f, a5 = 0.f, a6 = 0.f, a7 = 0.f;
#pragma unroll
    for (int g = 0; g < 4; g++) {
        __half2 h0 = __half2half2(__ushort_as_half(0));
        __half2 h1 = h0, h2 = h0, h3 = h0;
#pragma unroll
        for (int k2 = 0; k2 < 2; k2++) {
            const uint4 mm = *reinterpret_cast<const uint4*>(mrow + g * 4 + k2 * 2);
            {
                const __half2 w2 = *reinterpret_cast<const __half2*>(&mm.y);
                const uint4 v = *reinterpret_cast<const uint4*>(vbc + mm.x);
                h0 = __hfma2(w2, *reinterpret_cast<const __half2*>(&v.x), h0);
                h1 = __hfma2(w2, *reinterpret_cast<const __half2*>(&v.y), h1);
                h2 = __hfma2(w2, *reinterpret_cast<const __half2*>(&v.z), h2);
                h3 = __hfma2(w2, *reinterpret_cast<const __half2*>(&v.w), h3);
            }
            {
                const __half2 w2 = *reinterpret_cast<const __half2*>(&mm.w);
                const uint4 v = *reinterpret_cast<const uint4*>(vbc + mm.z);
                h0 = __hfma2(w2, *reinterpret_cast<const __half2*>(&v.x), h0);
                h1 = __hfma2(w2, *reinterpret_cast<const __half2*>(&v.y), h1);
                h2 = __hfma2(w2, *reinterpret_cast<const __half2*>(&v.z), h2);
                h3 = __hfma2(w2, *reinterpret_cast<const __half2*>(&v.w), h3);
            }
        }
        float2 f0 = __half22float2(h0), f1 = __half22float2(h1);
        float2 f2 = __half22float2(h2), f3 = __half22float2(h3);
        a0 += f0.x; a1 += f0.y; a2 += f1.x; a3 += f1.y;
        a4 += f2.x; a5 += f2.y; a6 += f3.x; a7 += f3.y;
    }
#pragma unroll
    for (int o = 4; o <= 16; o <<= 1) {
        a0 += __shfl_xor_sync(0xFFFFFFFFu, a0, o);
        a1 += __shfl_xor_sync(0xFFFFFFFFu, a1, o);
        a2 += __shfl_xor_sync(0xFFFFFFFFu, a2, o);
        a3 += __shfl_xor_sync(0xFFFFFFFFu, a3, o);
        a4 += __shfl_xor_sync(0xFFFFFFFFu, a4, o);
        a5 += __shfl_xor_sync(0xFFFFFFFFu, a5, o);
        a6 += __shfl_xor_sync(0xFFFFFFFFu, a6, o);
        a7 += __shfl_xor_sync(0xFFFFFFFFu, a7, o);
    }
    if (lane < 4) {
        float* op = out + (size_t)bq * 256 + h * 32 + lane * 8;
        *reinterpret_cast<float4*>(op) = make_float4(a0, a1, a2, a3);
        *reinterpret_cast<float4*>(op + 4) = make_float4(a4, a5, a6, a7);
    }
}

// ---------------------------------------------------------------------------
extern "C" void kernel_launch(void* const* d_in, const int* in_sizes, int n_in,
                              void* d_out, int out_size)
{
    const float* query = (const float*)d_in[0];
    const float* value = (const float*)d_in[1];
    const float* ref   = (const float*)d_in[2];
    const float* w_off = (const float*)d_in[3];
    const float* b_off = (const float*)d_in[4];
    const float* w_att = (const float*)d_in[5];
    const float* b_att = (const float*)d_in[6];
    const float* w_val = (const float*)d_in[7];
    const float* b_val = (const float*)d_in[8];
    float* out = (float*)d_out;

    static float* p_oa = nullptr;
    static __half* p_wth;
    if (!p_oa) {
        cudaGetSymbolAddress((void**)&p_oa, g_oa);
        cudaGetSymbolAddress((void**)&p_wth, g_wth);
        cudaFuncSetAttribute(gemm_merged, cudaFuncAttributeMaxDynamicSharedMemorySize, SMEM_TOTAL);
    }

    wprep_kernel<<<262144 / 256, 256>>>(w_val, w_off, w_att, p_wth);
    gemm_merged<<<NQ_TILES + NV_TILES, 256, SMEM_TOTAL>>>(
        query, value, p_wth, b_off, b_att, b_val, p_oa);
    sample_kernel<<<BB * QQ * NHH / 8, 256>>>(ref, out);
}

// round 15
// speedup vs baseline: 1.1253x; 1.1253x over previous
#include <cuda_runtime.h>
#include <cuda_fp16.h>
#include <math.h>
#include <stdint.h>

#define BB 4
#define QQ 10000
#define EE 256
#define NHH 8
#define S_TOTAL 19560

__constant__ int c_HL[4] = {92, 46, 23, 12};
__constant__ int c_WL[4] = {160, 80, 40, 20};
__constant__ int c_ST[4] = {0, 14720, 18400, 19320};

// Scratch (no cudaMalloc allowed)
__device__ __half g_vdup[BB * NHH * S_TOTAL * 64]; // pixel pairs {v[p], v[p+1]}, 128B each
__device__ float g_oa[BB * QQ * 768];              // [off(512) | attn(256)] per (b,q)
__device__ __half g_wth[262144];                   // weights fp16 [n][k]: val(256) | off+attn(768)

__device__ __forceinline__ uint32_t smem_u32(const void* p) {
    uint32_t a;
    asm("{ .reg .u64 t; cvta.to.shared.u64 t, %1; cvt.u32.u64 %0, t; }" : "=r"(a) : "l"(p));
    return a;
}

#define LDMATRIX_X4(r, addr) \
    asm volatile("ldmatrix.sync.aligned.m8n8.x4.shared.b16 {%0,%1,%2,%3}, [%4];" \
        : "=r"((r)[0]), "=r"((r)[1]), "=r"((r)[2]), "=r"((r)[3]) : "r"(addr))

#define MMA_F16(d, a, b) \
    asm volatile("mma.sync.aligned.m16n8k16.row.col.f32.f16.f16.f32 " \
        "{%0,%1,%2,%3}, {%4,%5,%6,%7}, {%8,%9}, {%0,%1,%2,%3};" \
        : "+f"((d)[0]), "+f"((d)[1]), "+f"((d)[2]), "+f"((d)[3]) \
        : "r"((a)[0]), "r"((a)[1]), "r"((a)[2]), "r"((a)[3]), "r"((b)[0]), "r"((b)[1]))

// ------------------------- weight prep (tiny) --------------------------------
__global__ __launch_bounds__(256) void wprep_kernel(
    const float* __restrict__ w_val, const float* __restrict__ w_off,
    const float* __restrict__ w_att, __half* __restrict__ th)
{
    int idx = blockIdx.x * 256 + threadIdx.x;
    float v;
    if (idx < 65536) {
        int n = idx >> 8, k = idx & 255;
        v = w_val[k * 256 + n];
    } else {
        int j = idx - 65536;
        int n = j >> 8, k = j & 255;
        v = (n < 512) ? w_off[k * 512 + n] : w_att[k * 256 + (n - 512)];
    }
    th[idx] = __float2half_rn(v);
}

// ------------------------- fused-convert fp16 GEMM, K-chunk 32 ---------------
#define A32_STRIDE 144
#define A32_TILE   (128 * A32_STRIDE)
#define A16_STRIDE 80
#define A16_TILE   (128 * A16_STRIDE)
#define B_TILE     10240
#define OFF_A16    (2 * A32_TILE)
#define OFF_B      (OFF_A16 + A16_TILE)
#define SMEM_TOTAL (OFF_B + 3 * B_TILE)

__device__ __forceinline__ int bdiv_s(int m) {
    return (m >= 2 * S_TOTAL) ? (m >= 3 * S_TOTAL ? 3 : 2) : (m >= S_TOTAL ? 1 : 0);
}

__device__ __forceinline__ void load_stage(
    uint32_t sbase, int a_stage, int b_stage,
    const char* A, const char* Bm, int bm, int bn, int M, int c, int tid)
{
    const uint32_t adst0 = sbase + a_stage * A32_TILE;
#pragma unroll
    for (int it = 0; it < 4; it++) {
        int idx = tid + it * 256;
        int row = idx >> 3;
        int g = (idx & 7) << 4;
        uint32_t dst = adst0 + row * A32_STRIDE + g;
        const char* src = A + (size_t)(bm + row) * 1024 + c * 128 + g;
        int ssize = (bm + row < M) ? 16 : 0;
        asm volatile("cp.async.ca.shared.global [%0], [%1], 16, %2;"
                     :: "r"(dst), "l"(src), "r"(ssize) : "memory");
    }
    const uint32_t bdst0 = sbase + OFF_B + b_stage * B_TILE;
#pragma unroll
    for (int it = 0; it < 2; it++) {
        int idx = tid + it * 256;
        int row = idx >> 2;
        int g = (idx & 3) << 4;
        uint32_t dst = bdst0 + row * A16_STRIDE + g;
        const char* src = Bm + (size_t)(bn + row) * 512 + c * 64 + g;
        asm volatile("cp.async.ca.shared.global [%0], [%1], 16, 16;"
                     :: "r"(dst), "l"(src) : "memory");
    }
}

// mode 0: C[m][n] = acc + bias (bias1 for n<bsplit, bias2 for n>=bsplit)
// mode 1: value path — dual-write fp16 pairs into g_vdup
__global__ __launch_bounds__(256, 2) void gemm_mma(
    const float* __restrict__ A_g, const __half* __restrict__ B_g,
    const float* __restrict__ bias1, const float* __restrict__ bias2, int bsplit,
    float* __restrict__ C, int M, int N, int mode)
{
    extern __shared__ char smem[];
    const uint32_t sbase = smem_u32(smem);
    const int tid = threadIdx.x;
    const int wid = tid >> 5, lane = tid & 31;
    const int warp_m = wid >> 2, warp_n = wid & 3;
    const int bm = blockIdx.y * 128, bn = blockIdx.x * 128;

    const char* Ac = reinterpret_cast<const char*>(A_g);
    const char* Bc = reinterpret_cast<const char*>(B_g);

    float acc[4][4][4];
#pragma unroll
    for (int mt = 0; mt < 4; mt++)
#pragma unroll
        for (int nt = 0; nt < 4; nt++)
#pragma unroll
            for (int r = 0; r < 4; r++) acc[mt][nt][r] = 0.f;

    load_stage(sbase, 0, 0, Ac, Bc, bm, bn, M, 0, tid);
    asm volatile("cp.async.commit_group;" ::: "memory");
    load_stage(sbase, 1, 1, Ac, Bc, bm, bn, M, 1, tid);
    asm volatile("cp.async.commit_group;" ::: "memory");

    const uint32_t a_row = warp_m * 64 + (lane & 15);
    const uint32_t a_off = (uint32_t)((lane >> 4) << 4);
    const uint32_t b_row = warp_n * 32 + (lane & 7) + ((lane >> 4) << 3);
    const uint32_t b_off = (uint32_t)(((lane >> 3) & 1) << 4);

    const int cv_row = tid >> 1;
    const int cv_sel = tid & 1;

    int b_rd = 0, b_wr = 2;
#pragma unroll 1
    for (int c = 0; c < 8; c++) {
        asm volatile("cp.async.wait_group 1;" ::: "memory");
        __syncthreads();

        // ---- convert A fp32 -> fp16 ----
        {
            const char* srcp = smem + (c & 1) * A32_TILE + cv_row * A32_STRIDE + cv_sel * 64;
            float4 f0 = *reinterpret_cast<const float4*>(srcp + 0);
            float4 f1 = *reinterpret_cast<const float4*>(srcp + 16);
            float4 f2 = *reinterpret_cast<const float4*>(srcp + 32);
            float4 f3 = *reinterpret_cast<const float4*>(srcp + 48);
            __half2 h0 = __floats2half2_rn(f0.x, f0.y), h1 = __floats2half2_rn(f0.z, f0.w);
            __half2 h2 = __floats2half2_rn(f1.x, f1.y), h3 = __floats2half2_rn(f1.z, f1.w);
            __half2 h4 = __floats2half2_rn(f2.x, f2.y), h5 = __floats2half2_rn(f2.z, f2.w);
            __half2 h6 = __floats2half2_rn(f3.x, f3.y), h7 = __floats2half2_rn(f3.z, f3.w);
            char* dstp = smem + OFF_A16 + cv_row * A16_STRIDE + cv_sel * 32;
            *reinterpret_cast<uint4*>(dstp) = make_uint4(
                *reinterpret_cast<uint32_t*>(&h0), *reinterpret_cast<uint32_t*>(&h1),
                *reinterpret_cast<uint32_t*>(&h2), *reinterpret_cast<uint32_t*>(&h3));
            *reinterpret_cast<uint4*>(dstp + 16) = make_uint4(
                *reinterpret_cast<uint32_t*>(&h4), *reinterpret_cast<uint32_t*>(&h5),
                *reinterpret_cast<uint32_t*>(&h6), *reinterpret_cast<uint32_t*>(&h7));
        }
        __syncthreads();

        if (c + 2 < 8)
            load_stage(sbase, c & 1, b_wr, Ac, Bc, bm, bn, M, c + 2, tid);
        asm volatile("cp.async.commit_group;" ::: "memory");

        const uint32_t sa = sbase + OFF_A16;
        const uint32_t sb = sbase + OFF_B + b_rd * B_TILE;
        uint32_t ah[4][4], bh[4][2];
#pragma unroll
        for (int mt = 0; mt < 4; mt++)
            LDMATRIX_X4(ah[mt], sa + (a_row + mt * 16) * A16_STRIDE + a_off);
#pragma unroll
        for (int g = 0; g < 2; g++) {
            uint32_t rh[4];
            LDMATRIX_X4(rh, sb + (b_row + g * 16) * A16_STRIDE + b_off);
            bh[2 * g][0] = rh[0]; bh[2 * g][1] = rh[1];
            bh[2 * g + 1][0] = rh[2]; bh[2 * g + 1][1] = rh[3];
        }
#pragma unroll
        for (int mt = 0; mt < 4; mt++)
#pragma unroll
            for (int nt = 0; nt < 4; nt++)
                MMA_F16(acc[mt][nt], ah[mt], bh[nt]);

#pragma unroll
        for (int mt = 0; mt < 4; mt++)
            LDMATRIX_X4(ah[mt], sa + (a_row + mt * 16) * A16_STRIDE + 32 + a_off);
#pragma unroll
        for (int g = 0; g < 2; g++) {
            uint32_t rh[4];
            LDMATRIX_X4(rh, sb + (b_row + g * 16) * A16_STRIDE + 32 + b_off);
            bh[2 * g][0] = rh[0]; bh[2 * g][1] = rh[1];
            bh[2 * g + 1][0] = rh[2]; bh[2 * g + 1][1] = rh[3];
        }
#pragma unroll
        for (int mt = 0; mt < 4; mt++)
#pragma unroll
            for (int nt = 0; nt < 4; nt++)
                MMA_F16(acc[mt][nt], ah[mt], bh[nt]);

        b_rd = (b_rd == 2) ? 0 : b_rd + 1;
        b_wr = (b_wr == 2) ? 0 : b_wr + 1;
    }

    const int q = lane >> 2, t = lane & 3;
    if (mode == 0) {
#pragma unroll
        for (int mt = 0; mt < 4; mt++) {
            int m0 = bm + warp_m * 64 + mt * 16 + q;
#pragma unroll
            for (int nt = 0; nt < 4; nt++) {
                int n = bn + warp_n * 32 + nt * 8 + 2 * t;
                float b0 = (n < bsplit) ? bias1[n] : bias2[n - bsplit];
                float b1 = (n + 1 < bsplit) ? bias1[n + 1] : bias2[n + 1 - bsplit];
                if (m0 < M)
                    *reinterpret_cast<float2*>(C + (size_t)m0 * N + n) =
                        make_float2(acc[mt][nt][0] + b0, acc[mt][nt][1] + b1);
                if (m0 + 8 < M)
                    *reinterpret_cast<float2*>(C + (size_t)(m0 + 8) * N + n) =
                        make_float2(acc[mt][nt][2] + b0, acc[mt][nt][3] + b1);
            }
        }
    } else {
        __half2* vf = reinterpret_cast<__half2*>(g_vdup);
#pragma unroll
        for (int mt = 0; mt < 4; mt++) {
            int m0 = bm + warp_m * 64 + mt * 16 + q;
#pragma unroll
            for (int nt = 0; nt < 4; nt++) {
                int n = bn + warp_n * 32 + nt * 8 + 2 * t;
                int h = n >> 5, d = n & 31;
                float b0 = bias1[n], b1 = bias1[n + 1];
#pragma unroll
                for (int rr = 0; rr < 2; rr++) {
                    int m = m0 + rr * 8;
                    if (m < M) {
                        int bb = bdiv_s(m);
                        int s = m - bb * S_TOTAL;
                        size_t ip = (size_t)(bb * 8 + h) * S_TOTAL + s;
                        __half2 hv = __floats2half2_rn(acc[mt][nt][2 * rr] + b0,
                                                       acc[mt][nt][2 * rr + 1] + b1);
                        vf[ip * 32 + (d >> 1)] = hv;
                        if (s > 0)
                            vf[(ip - 1) * 32 + 16 + (d >> 1)] = hv;
                    }
                }
            }
        }
    }
}

// ------------------------- fused softmax + sampling -------------------------
// Meta: 8 groups (midx x parity) per warp at 144B stride (18 uint2; 16 used).
// Group bases mod 128B = {0,16,32,...,112} -> the 8 uint4 reads per LDS.128
// phase cover all 32 banks exactly once (conflict-free, single wavefront).
// Phase 2: per 2 iterations one LDS.128 {addr0,w0,addr1,w1} + 2 LDG.128 + 8 HFMA2.
__global__ __launch_bounds__(256, 8) void sample_kernel(
    const float* __restrict__ ref, float* __restrict__ out)
{
    __shared__ uint2 sMeta[8][144];

    const int w = threadIdx.x >> 5;
    const int lane = threadIdx.x & 31;
    const int warp_global = blockIdx.x * 8 + w;
    const int h = warp_global & 7;
    const int bq = warp_global >> 3;
    const int b = bq / QQ;

    float logit = g_oa[(size_t)bq * 768 + 512 + h * 32 + lane];
    float m = logit;
#pragma unroll
    for (int o = 16; o; o >>= 1) m = fmaxf(m, __shfl_xor_sync(0xFFFFFFFFu, m, o));
    float e = __expf(logit - m);
    float s = e;
#pragma unroll
    for (int o = 16; o; o >>= 1) s += __shfl_xor_sync(0xFFFFFFFFu, s, o);
    const float aw = e / s;

    const int l = lane >> 3;
    const int p = lane & 7;
    const int z = p & 3;
    const float2 off2 = *reinterpret_cast<const float2*>(g_oa + (size_t)bq * 768 + h * 64 + lane * 2);
    const float2 r2 = *reinterpret_cast<const float2*>(ref + ((size_t)bq * 4 + z) * 2);
    const int W = c_WL[l], H = c_HL[l], st = c_ST[l];
    const float px = r2.x * (float)W + off2.x - 0.5f;
    const float py = r2.y * (float)H + off2.y - 0.5f;
    const float x0f = floorf(px), y0f = floorf(py);
    const int x0 = (int)x0f, y0 = (int)y0f;
    const float fx = px - x0f, fy = py - y0f;
    const float gx = 1.f - fx, gy = 1.f - fy;
    const bool xi0 = (x0 >= 0) && (x0 < W);
    const bool yi0 = (y0 >= 0) && (y0 < H);
    const bool yi1 = (y0 >= -1) && (y0 < H - 1);
    const int bx = min(max(x0, 0), W - 1);
    const int yc0 = min(max(y0, 0), H - 1);
    const int yc1 = min(max(y0 + 1, 0), H - 1);

    const float wf = xi0 ? gx : ((x0 == -1) ? fx : 0.f);
    const float ws = (xi0 && (x0 + 1 < W)) ? fx : 0.f;
    const float wy0 = yi0 ? aw * gy : 0.f;
    const float wy1 = yi1 ? aw * fy : 0.f;

    const uint32_t basepix = (uint32_t)(b * 8 + h) * (uint32_t)S_TOTAL;
    const uint32_t aT = (basepix + (uint32_t)(st + yc0 * W + bx)) << 7;
    const uint32_t aB = (basepix + (uint32_t)(st + yc1 * W + bx)) << 7;
    {
        __half2 d0 = __half2half2(__float2half_rn(wy0 * wf));
        __half2 d1 = __half2half2(__float2half_rn(wy0 * ws));
        __half2 d2 = __half2half2(__float2half_rn(wy1 * wf));
        __half2 d3 = __half2half2(__float2half_rn(wy1 * ws));
        const int parity = lane & 1;     // point parity
        const int itw = lane >> 1;       // iteration slot (0..15)
        sMeta[w][(0 * 2 + parity) * 18 + itw] = make_uint2(aT, *reinterpret_cast<uint32_t*>(&d0));
        sMeta[w][(1 * 2 + parity) * 18 + itw] = make_uint2(aT, *reinterpret_cast<uint32_t*>(&d1));
        sMeta[w][(2 * 2 + parity) * 18 + itw] = make_uint2(aB, *reinterpret_cast<uint32_t*>(&d2));
        sMeta[w][(3 * 2 + parity) * 18 + itw] = make_uint2(aB, *reinterpret_cast<uint32_t*>(&d3));
    }
    __syncwarp();

    const int half = lane >> 4;
    const int midx = (lane >> 2) & 3;
    const uint32_t coff = (uint32_t)(lane & 7) * 16;
    const char* vbc = reinterpret_cast<const char*>(g_vdup) + coff;
    const uint2* mrow = &sMeta[w][(midx * 2 + half) * 18];

    float a0 = 0.f, a1 = 0.f, a2 = 0.f, a3 = 0.f, a4 = 0.f, a5 = 0.f, a6 = 0.f, a7 = 0.f;
#pragma unroll
    for (int g = 0; g < 4; g++) {
        __half2 h0 = __half2half2(__ushort_as_half(0));
        __half2 h1 = h0, h2 = h0, h3 = h0;
#pragma unroll
        for (int k2 = 0; k2 < 2; k2++) {
            const uint4 mm = *reinterpret_cast<const uint4*>(mrow + g * 4 + k2 * 2);
            {
                const __half2 w2 = *reinterpret_cast<const __half2*>(&mm.y);
                const uint4 v = *reinterpret_cast<const uint4*>(vbc + mm.x);
                h0 = __hfma2(w2, *reinterpret_cast<const __half2*>(&v.x), h0);
                h1 = __hfma2(w2, *reinterpret_cast<const __half2*>(&v.y), h1);
                h2 = __hfma2(w2, *reinterpret_cast<const __half2*>(&v.z), h2);
                h3 = __hfma2(w2, *reinterpret_cast<const __half2*>(&v.w), h3);
            }
            {
                const __half2 w2 = *reinterpret_cast<const __half2*>(&mm.w);
                const uint4 v = *reinterpret_cast<const uint4*>(vbc + mm.z);
                h0 = __hfma2(w2, *reinterpret_cast<const __half2*>(&v.x), h0);
                h1 = __hfma2(w2, *reinterpret_cast<const __half2*>(&v.y), h1);
                h2 = __hfma2(w2, *reinterpret_cast<const __half2*>(&v.z), h2);
                h3 = __hfma2(w2, *reinterpret_cast<const __half2*>(&v.w), h3);
            }
        }
        float2 f0 = __half22float2(h0), f1 = __half22float2(h1);
        float2 f2 = __half22float2(h2), f3 = __half22float2(h3);
        a0 += f0.x; a1 += f0.y; a2 += f1.x; a3 += f1.y;
        a4 += f2.x; a5 += f2.y; a6 += f3.x; a7 += f3.y;
    }
#pragma unroll
    for (int o = 4; o <= 16; o <<= 1) {
        a0 += __shfl_xor_sync(0xFFFFFFFFu, a0, o);
        a1 += __shfl_xor_sync(0xFFFFFFFFu, a1, o);
        a2 += __shfl_xor_sync(0xFFFFFFFFu, a2, o);
        a3 += __shfl_xor_sync(0xFFFFFFFFu, a3, o);
        a4 += __shfl_xor_sync(0xFFFFFFFFu, a4, o);
        a5 += __shfl_xor_sync(0xFFFFFFFFu, a5, o);
        a6 += __shfl_xor_sync(0xFFFFFFFFu, a6, o);
        a7 += __shfl_xor_sync(0xFFFFFFFFu, a7, o);
    }
    if (lane < 4) {
        float* op = out + (size_t)bq * 256 + h * 32 + lane * 8;
        *reinterpret_cast<float4*>(op) = make_float4(a0, a1, a2, a3);
        *reinterpret_cast<float4*>(op + 4) = make_float4(a4, a5, a6, a7);
    }
}

// ---------------------------------------------------------------------------
extern "C" void kernel_launch(void* const* d_in, const int* in_sizes, int n_in,
                              void* d_out, int out_size)
{
    const float* query = (const float*)d_in[0];
    const float* value = (const float*)d_in[1];
    const float* ref   = (const float*)d_in[2];
    const float* w_off = (const float*)d_in[3];
    const float* b_off = (const float*)d_in[4];
    const float* w_att = (const float*)d_in[5];
    const float* b_att = (const float*)d_in[6];
    const float* w_val = (const float*)d_in[7];
    const float* b_val = (const float*)d_in[8];
    float* out = (float*)d_out;

    static float* p_oa = nullptr;
    static __half* p_wth;
    static cudaStream_t s1;
    static cudaEvent_t e0, e1;
    if (!p_oa) {
        cudaGetSymbolAddress((void**)&p_oa, g_oa);
        cudaGetSymbolAddress((void**)&p_wth, g_wth);
        cudaFuncSetAttribute(gemm_mma, cudaFuncAttributeMaxDynamicSharedMemorySize, SMEM_TOTAL);
        cudaStreamCreateWithFlags(&s1, cudaStreamNonBlocking);
        cudaEventCreateWithFlags(&e0, cudaEventDisableTiming);
        cudaEventCreateWithFlags(&e1, cudaEventDisableTiming);
    }

    // tiny weight prep, then fork the two GEMM chains
    wprep_kernel<<<262144 / 256, 256>>>(w_val, w_off, w_att, p_wth);
    cudaEventRecord(e0, 0);
    cudaStreamWaitEvent(s1, e0, 0);

    // query GEMM (off+attn, N=768) on s1 — A = query fp32, converted in-kernel
    {
        dim3 grid(6, (BB * QQ + 127) / 128);
        gemm_mma<<<grid, 256, SMEM_TOTAL, s1>>>(query, p_wth + 65536, b_off, b_att, 512,
                                                p_oa, BB * QQ, 768, 0);
    }
    // value GEMM on main stream — A = value fp32, converted in-kernel
    {
        dim3 grid(2, (BB * S_TOTAL + 127) / 128);
        gemm_mma<<<grid, 256, SMEM_TOTAL>>>(value, p_wth, b_val, b_val, 1 << 30,
                                            nullptr, BB * S_TOTAL, 256, 1);
    }

    // join
    cudaEventRecord(e1, s1);
    cudaStreamWaitEvent(0, e1, 0);

    sample_kernel<<<BB * QQ * NHH / 8, 256>>>(ref, out);
}

// round 17
// speedup vs baseline: 1.1832x; 1.0514x over previous
#include <cuda_runtime.h>
#include <cuda_fp16.h>
#include <math.h>
#include <stdint.h>

#define BB 4
#define QQ 10000
#define EE 256
#define NHH 8
#define S_TOTAL 19560

__constant__ int c_HL[4] = {92, 46, 23, 12};
__constant__ int c_WL[4] = {160, 80, 40, 20};
__constant__ int c_ST[4] = {0, 14720, 18400, 19320};

// Scratch (no cudaMalloc allowed)
__device__ __half g_vdup[BB * NHH * S_TOTAL * 64]; // pixel pairs {v[p], v[p+1]}, 128B each
__device__ float g_oa[BB * QQ * 768];              // [off(512) | attn(256)] per (b,q)
__device__ __half g_wth[262144];                   // weights fp16 [n][k]: val(256) | off+attn(768)

__device__ __forceinline__ uint32_t smem_u32(const void* p) {
    uint32_t a;
    asm("{ .reg .u64 t; cvta.to.shared.u64 t, %1; cvt.u32.u64 %0, t; }" : "=r"(a) : "l"(p));
    return a;
}

#define LDMATRIX_X4(r, addr) \
    asm volatile("ldmatrix.sync.aligned.m8n8.x4.shared.b16 {%0,%1,%2,%3}, [%4];" \
        : "=r"((r)[0]), "=r"((r)[1]), "=r"((r)[2]), "=r"((r)[3]) : "r"(addr))

#define MMA_F16(d, a, b) \
    asm volatile("mma.sync.aligned.m16n8k16.row.col.f32.f16.f16.f32 " \
        "{%0,%1,%2,%3}, {%4,%5,%6,%7}, {%8,%9}, {%0,%1,%2,%3};" \
        : "+f"((d)[0]), "+f"((d)[1]), "+f"((d)[2]), "+f"((d)[3]) \
        : "r"((a)[0]), "r"((a)[1]), "r"((a)[2]), "r"((a)[3]), "r"((b)[0]), "r"((b)[1]))

// ------------------------- weight prep (split per stream) -------------------
__global__ __launch_bounds__(256) void wprepV_kernel(
    const float* __restrict__ w_val, __half* __restrict__ th)
{
    int idx = blockIdx.x * 256 + threadIdx.x;   // 65536
    int n = idx >> 8, k = idx & 255;
    th[idx] = __float2half_rn(w_val[k * 256 + n]);
}

__global__ __launch_bounds__(256) void wprepQ_kernel(
    const float* __restrict__ w_off, const float* __restrict__ w_att,
    __half* __restrict__ th)
{
    int idx = blockIdx.x * 256 + threadIdx.x;   // 196608
    int n = idx >> 8, k = idx & 255;
    float v = (n < 512) ? w_off[k * 512 + n] : w_att[k * 256 + (n - 512)];
    th[idx] = __float2half_rn(v);
}

// ------------------------- fused-convert fp16 GEMM, K-chunk 32 ---------------
#define A32_STRIDE 144
#define A32_TILE   (128 * A32_STRIDE)
#define A16_STRIDE 80
#define A16_TILE   (128 * A16_STRIDE)
#define B_TILE     10240
#define OFF_A16    (2 * A32_TILE)
#define OFF_B      (OFF_A16 + A16_TILE)
#define SMEM_TOTAL (OFF_B + 3 * B_TILE)

// epilogue staging stride: 128 cols fp16 = 256B payload + 16B pad
#define EP_STRIDE_B 272
#define EP_STRIDE_H2 68

__device__ __forceinline__ int bdiv_s(int m) {
    return (m >= 2 * S_TOTAL) ? (m >= 3 * S_TOTAL ? 3 : 2) : (m >= S_TOTAL ? 1 : 0);
}

__device__ __forceinline__ void load_stage(
    uint32_t sbase, int a_stage, int b_stage,
    const char* A, const char* Bm, int bm, int bn, int M, int c, int tid)
{
    const uint32_t adst0 = sbase + a_stage * A32_TILE;
#pragma unroll
    for (int it = 0; it < 4; it++) {
        int idx = tid + it * 256;
        int row = idx >> 3;
        int g = (idx & 7) << 4;
        uint32_t dst = adst0 + row * A32_STRIDE + g;
        const char* src = A + (size_t)(bm + row) * 1024 + c * 128 + g;
        int ssize = (bm + row < M) ? 16 : 0;
        asm volatile("cp.async.ca.shared.global [%0], [%1], 16, %2;"
                     :: "r"(dst), "l"(src), "r"(ssize) : "memory");
    }
    const uint32_t bdst0 = sbase + OFF_B + b_stage * B_TILE;
#pragma unroll
    for (int it = 0; it < 2; it++) {
        int idx = tid + it * 256;
        int row = idx >> 2;
        int g = (idx & 3) << 4;
        uint32_t dst = bdst0 + row * A16_STRIDE + g;
        const char* src = Bm + (size_t)(bn + row) * 512 + c * 64 + g;
        asm volatile("cp.async.ca.shared.global [%0], [%1], 16, 16;"
                     :: "r"(dst), "l"(src) : "memory");
    }
}

// mode 0: C[m][n] = acc + bias (bias1 for n<bsplit, bias2 for n>=bsplit)
// mode 1: value path — smem-staged coalesced pair writes into g_vdup
__global__ __launch_bounds__(256, 2) void gemm_mma(
    const float* __restrict__ A_g, const __half* __restrict__ B_g,
    const float* __restrict__ bias1, const float* __restrict__ bias2, int bsplit,
    float* __restrict__ C, int M, int N, int mode)
{
    extern __shared__ char smem[];
    const uint32_t sbase = smem_u32(smem);
    const int tid = threadIdx.x;
    const int wid = tid >> 5, lane = tid & 31;
    const int warp_m = wid >> 2, warp_n = wid & 3;
    const int bm = blockIdx.y * 128, bn = blockIdx.x * 128;

    const char* Ac = reinterpret_cast<const char*>(A_g);
    const char* Bc = reinterpret_cast<const char*>(B_g);

    float acc[4][4][4];
#pragma unroll
    for (int mt = 0; mt < 4; mt++)
#pragma unroll
        for (int nt = 0; nt < 4; nt++)
#pragma unroll
            for (int r = 0; r < 4; r++) acc[mt][nt][r] = 0.f;

    load_stage(sbase, 0, 0, Ac, Bc, bm, bn, M, 0, tid);
    asm volatile("cp.async.commit_group;" ::: "memory");
    load_stage(sbase, 1, 1, Ac, Bc, bm, bn, M, 1, tid);
    asm volatile("cp.async.commit_group;" ::: "memory");

    const uint32_t a_row = warp_m * 64 + (lane & 15);
    const uint32_t a_off = (uint32_t)((lane >> 4) << 4);
    const uint32_t b_row = warp_n * 32 + (lane & 7) + ((lane >> 4) << 3);
    const uint32_t b_off = (uint32_t)(((lane >> 3) & 1) << 4);

    const int cv_row = tid >> 1;
    const int cv_sel = tid & 1;

    int b_rd = 0, b_wr = 2;
#pragma unroll 1
    for (int c = 0; c < 8; c++) {
        asm volatile("cp.async.wait_group 1;" ::: "memory");
        __syncthreads();

        // ---- convert A fp32 -> fp16 ----
        {
            const char* srcp = smem + (c & 1) * A32_TILE + cv_row * A32_STRIDE + cv_sel * 64;
            float4 f0 = *reinterpret_cast<const float4*>(srcp + 0);
            float4 f1 = *reinterpret_cast<const float4*>(srcp + 16);
            float4 f2 = *reinterpret_cast<const float4*>(srcp + 32);
            float4 f3 = *reinterpret_cast<const float4*>(srcp + 48);
            __half2 h0 = __floats2half2_rn(f0.x, f0.y), h1 = __floats2half2_rn(f0.z, f0.w);
            __half2 h2 = __floats2half2_rn(f1.x, f1.y), h3 = __floats2half2_rn(f1.z, f1.w);
            __half2 h4 = __floats2half2_rn(f2.x, f2.y), h5 = __floats2half2_rn(f2.z, f2.w);
            __half2 h6 = __floats2half2_rn(f3.x, f3.y), h7 = __floats2half2_rn(f3.z, f3.w);
            char* dstp = smem + OFF_A16 + cv_row * A16_STRIDE + cv_sel * 32;
            *reinterpret_cast<uint4*>(dstp) = make_uint4(
                *reinterpret_cast<uint32_t*>(&h0), *reinterpret_cast<uint32_t*>(&h1),
                *reinterpret_cast<uint32_t*>(&h2), *reinterpret_cast<uint32_t*>(&h3));
            *reinterpret_cast<uint4*>(dstp + 16) = make_uint4(
                *reinterpret_cast<uint32_t*>(&h4), *reinterpret_cast<uint32_t*>(&h5),
                *reinterpret_cast<uint32_t*>(&h6), *reinterpret_cast<uint32_t*>(&h7));
        }
        __syncthreads();

        if (c + 2 < 8)
            load_stage(sbase, c & 1, b_wr, Ac, Bc, bm, bn, M, c + 2, tid);
        asm volatile("cp.async.commit_group;" ::: "memory");

        const uint32_t sa = sbase + OFF_A16;
        const uint32_t sb = sbase + OFF_B + b_rd * B_TILE;
        uint32_t ah[4][4], bh[4][2];
#pragma unroll
        for (int mt = 0; mt < 4; mt++)
            LDMATRIX_X4(ah[mt], sa + (a_row + mt * 16) * A16_STRIDE + a_off);
#pragma unroll
        for (int g = 0; g < 2; g++) {
            uint32_t rh[4];
            LDMATRIX_X4(rh, sb + (b_row + g * 16) * A16_STRIDE + b_off);
            bh[2 * g][0] = rh[0]; bh[2 * g][1] = rh[1];
            bh[2 * g + 1][0] = rh[2]; bh[2 * g + 1][1] = rh[3];
        }
#pragma unroll
        for (int mt = 0; mt < 4; mt++)
#pragma unroll
            for (int nt = 0; nt < 4; nt++)
                MMA_F16(acc[mt][nt], ah[mt], bh[nt]);

#pragma unroll
        for (int mt = 0; mt < 4; mt++)
            LDMATRIX_X4(ah[mt], sa + (a_row + mt * 16) * A16_STRIDE + 32 + a_off);
#pragma unroll
        for (int g = 0; g < 2; g++) {
            uint32_t rh[4];
            LDMATRIX_X4(rh, sb + (b_row + g * 16) * A16_STRIDE + 32 + b_off);
            bh[2 * g][0] = rh[0]; bh[2 * g][1] = rh[1];
            bh[2 * g + 1][0] = rh[2]; bh[2 * g + 1][1] = rh[3];
        }
#pragma unroll
        for (int mt = 0; mt < 4; mt++)
#pragma unroll
            for (int nt = 0; nt < 4; nt++)
                MMA_F16(acc[mt][nt], ah[mt], bh[nt]);

        b_rd = (b_rd == 2) ? 0 : b_rd + 1;
        b_wr = (b_wr == 2) ? 0 : b_wr + 1;
    }

    const int q = lane >> 2, t = lane & 3;
    if (mode == 0) {
#pragma unroll
        for (int mt = 0; mt < 4; mt++) {
            int m0 = bm + warp_m * 64 + mt * 16 + q;
#pragma unroll
            for (int nt = 0; nt < 4; nt++) {
                int n = bn + warp_n * 32 + nt * 8 + 2 * t;
                float b0 = (n < bsplit) ? bias1[n] : bias2[n - bsplit];
                float b1 = (n + 1 < bsplit) ? bias1[n + 1] : bias2[n + 1 - bsplit];
                if (m0 < M)
                    *reinterpret_cast<float2*>(C + (size_t)m0 * N + n) =
                        make_float2(acc[mt][nt][0] + b0, acc[mt][nt][1] + b1);
                if (m0 + 8 < M)
                    *reinterpret_cast<float2*>(C + (size_t)(m0 + 8) * N + n) =
                        make_float2(acc[mt][nt][2] + b0, acc[mt][nt][3] + b1);
            }
        }
    } else {
        // value path: stage acc+bias as fp16 in smem [128 rows][272B stride,
        // 256B payload], then emit each 128B pair entry {row p | row p+1}
        // with coalesced uint4 STGs.
        __syncthreads();
        __half2* ep = reinterpret_cast<__half2*>(smem);
#pragma unroll
        for (int mt = 0; mt < 4; mt++) {
            int ml = warp_m * 64 + mt * 16 + q;
#pragma unroll
            for (int nt = 0; nt < 4; nt++) {
                int nl = warp_n * 32 + nt * 8 + 2 * t;
                int n = bn + nl;
                float b0 = bias1[n], b1 = bias1[n + 1];
                ep[ml * EP_STRIDE_H2 + (nl >> 1)] =
                    __floats2half2_rn(acc[mt][nt][0] + b0, acc[mt][nt][1] + b1);
                ep[(ml + 8) * EP_STRIDE_H2 + (nl >> 1)] =
                    __floats2half2_rn(acc[mt][nt][2] + b0, acc[mt][nt][3] + b1);
            }
        }
        __syncthreads();

        const char* epc = reinterpret_cast<const char*>(smem);
        const int hh = (bn >> 5) + (lane >> 3);   // global head 0..7
        const int colb = (lane >> 3) * 64;        // byte col base for this head
        const int piece = lane & 7;               // 16B piece of the 128B entry
        char* vd = reinterpret_cast<char*>(g_vdup);
#pragma unroll 1
        for (int it = 0; it < 16; it++) {
            const int pl = wid + it * 8;          // local pair row 0..127
            const int m = bm + pl;
            if (piece < 4) {
                if (m < M) {
                    int bb = bdiv_s(m);
                    int s = m - bb * S_TOTAL;
                    size_t ipb = ((size_t)(bb * 8 + hh) * S_TOTAL + s) * 128;
                    const uint4 v = *reinterpret_cast<const uint4*>(
                        epc + pl * EP_STRIDE_B + colb + piece * 16);
                    *reinterpret_cast<uint4*>(vd + ipb + piece * 16) = v;
                }
            } else {
                if (pl == 127) {
                    // second half of previous tile's last pair (bm-1) from row 0
                    if (bm > 0) {
                        int mp = bm - 1;
                        int bb = bdiv_s(mp);
                        int s = mp - bb * S_TOTAL;
                        size_t ipb = ((size_t)(bb * 8 + hh) * S_TOTAL + s) * 128;
                        const uint4 v = *reinterpret_cast<const uint4*>(
                            epc + colb + (piece - 4) * 16);
                        *reinterpret_cast<uint4*>(vd + ipb + 64 + (piece - 4) * 16) = v;
                    }
                } else if (m + 1 < M) {
                    int bb = bdiv_s(m);
                    int s = m - bb * S_TOTAL;
                    size_t ipb = ((size_t)(bb * 8 + hh) * S_TOTAL + s) * 128;
                    const uint4 v = *reinterpret_cast<const uint4*>(
                        epc + (pl + 1) * EP_STRIDE_B + colb + (piece - 4) * 16);
                    *reinterpret_cast<uint4*>(vd + ipb + piece * 16) = v;
                }
            }
        }
    }
}

// ------------------------- fused softmax + sampling (R13 exact) -------------
__global__ __launch_bounds__(256, 8) void sample_kernel(
    const float* __restrict__ ref, float* __restrict__ out)
{
    __shared__ uint2 sMeta[8][128];

    const int w = threadIdx.x >> 5;
    const int lane = threadIdx.x & 31;
    const int warp_global = blockIdx.x * 8 + w;
    const int h = warp_global & 7;
    const int bq = warp_global >> 3;
    const int b = bq / QQ;

    float logit = g_oa[(size_t)bq * 768 + 512 + h * 32 + lane];
    float m = logit;
#pragma unroll
    for (int o = 16; o; o >>= 1) m = fmaxf(m, __shfl_xor_sync(0xFFFFFFFFu, m, o));
    float e = __expf(logit - m);
    float s = e;
#pragma unroll
    for (int o = 16; o; o >>= 1) s += __shfl_xor_sync(0xFFFFFFFFu, s, o);
    const float aw = e / s;

    const int l = lane >> 3;
    const int p = lane & 7;
    const int z = p & 3;
    const float2 off2 = *reinterpret_cast<const float2*>(g_oa + (size_t)bq * 768 + h * 64 + lane * 2);
    const float2 r2 = *reinterpret_cast<const float2*>(ref + ((size_t)bq * 4 + z) * 2);
    const int W = c_WL[l], H = c_HL[l], st = c_ST[l];
    const float px = r2.x * (float)W + off2.x - 0.5f;
    const float py = r2.y * (float)H + off2.y - 0.5f;
    const float x0f = floorf(px), y0f = floorf(py);
    const int x0 = (int)x0f, y0 = (int)y0f;
    const float fx = px - x0f, fy = py - y0f;
    const float gx = 1.f - fx, gy = 1.f - fy;
    const bool xi0 = (x0 >= 0) && (x0 < W);
    const bool yi0 = (y0 >= 0) && (y0 < H);
    const bool yi1 = (y0 >= -1) && (y0 < H - 1);
    const int bx = min(max(x0, 0), W - 1);
    const int yc0 = min(max(y0, 0), H - 1);
    const int yc1 = min(max(y0 + 1, 0), H - 1);

    const float wf = xi0 ? gx : ((x0 == -1) ? fx : 0.f);
    const float ws = (xi0 && (x0 + 1 < W)) ? fx : 0.f;
    const float wy0 = yi0 ? aw * gy : 0.f;
    const float wy1 = yi1 ? aw * fy : 0.f;

    const uint32_t basepix = (uint32_t)(b * 8 + h) * (uint32_t)S_TOTAL;
    const uint32_t aT = (basepix + (uint32_t)(st + yc0 * W + bx)) << 7;
    const uint32_t aB = (basepix + (uint32_t)(st + yc1 * W + bx)) << 7;
    {
        __half2 d0 = __half2half2(__float2half_rn(wy0 * wf));
        __half2 d1 = __half2half2(__float2half_rn(wy0 * ws));
        __half2 d2 = __half2half2(__float2half_rn(wy1 * wf));
        __half2 d3 = __half2half2(__float2half_rn(wy1 * ws));
        uint4* m4 = reinterpret_cast<uint4*>(&sMeta[w][0]);
        m4[lane * 2 + 0] = make_uint4(aT, *reinterpret_cast<uint32_t*>(&d0),
                                      aT, *reinterpret_cast<uint32_t*>(&d1));
        m4[lane * 2 + 1] = make_uint4(aB, *reinterpret_cast<uint32_t*>(&d2),
                                      aB, *reinterpret_cast<uint32_t*>(&d3));
    }
    __syncwarp();

    const int half = lane >> 4;
    const int midx = (lane >> 2) & 3;
    const uint32_t coff = (uint32_t)(lane & 7) * 16;
    const char* vbc = reinterpret_cast<const char*>(g_vdup) + coff;
    const uint2* mrow = &sMeta[w][midx];

    float a0 = 0.f, a1 = 0.f, a2 = 0.f, a3 = 0.f, a4 = 0.f, a5 = 0.f, a6 = 0.f, a7 = 0.f;
#pragma unroll
    for (int g = 0; g < 4; g++) {
        __half2 h0 = __half2half2(__ushort_as_half(0));
        __half2 h1 = h0, h2 = h0, h3 = h0;
#pragma unroll
        for (int k = 0; k < 4; k++) {
            const int j = 2 * (g * 4 + k) + half;
            const uint2 mt = mrow[j * 4];
            const __half2 w2 = *reinterpret_cast<const __half2*>(&mt.y);
            const uint4 v = *reinterpret_cast<const uint4*>(vbc + mt.x);
            h0 = __hfma2(w2, *reinterpret_cast<const __half2*>(&v.x), h0);
            h1 = __hfma2(w2, *reinterpret_cast<const __half2*>(&v.y), h1);
            h2 = __hfma2(w2, *reinterpret_cast<const __half2*>(&v.z), h2);
            h3 = __hfma2(w2, *reinterpret_cast<const __half2*>(&v.w), h3);
        }
        float2 f0 = __half22float2(h0), f1 = __half22float2(h1);
        float2 f2 = __half22float2(h2), f3 = __half22float2(h3);
        a0 += f0.x; a1 += f0.y; a2 += f1.x; a3 += f1.y;
        a4 += f2.x; a5 += f2.y; a6 += f3.x; a7 += f3.y;
    }
#pragma unroll
    for (int o = 4; o <= 16; o <<= 1) {
        a0 += __shfl_xor_sync(0xFFFFFFFFu, a0, o);
        a1 += __shfl_xor_sync(0xFFFFFFFFu, a1, o);
        a2 += __shfl_xor_sync(0xFFFFFFFFu, a2, o);
        a3 += __shfl_xor_sync(0xFFFFFFFFu, a3, o);
        a4 += __shfl_xor_sync(0xFFFFFFFFu, a4, o);
        a5 += __shfl_xor_sync(0xFFFFFFFFu, a5, o);
        a6 += __shfl_xor_sync(0xFFFFFFFFu, a6, o);
        a7 += __shfl_xor_sync(0xFFFFFFFFu, a7, o);
    }
    if (lane < 4) {
        float* op = out + (size_t)bq * 256 + h * 32 + lane * 8;
        *reinterpret_cast<float4*>(op) = make_float4(a0, a1, a2, a3);
        *reinterpret_cast<float4*>(op + 4) = make_float4(a4, a5, a6, a7);
    }
}

// ---------------------------------------------------------------------------
extern "C" void kernel_launch(void* const* d_in, const int* in_sizes, int n_in,
                              void* d_out, int out_size)
{
    const float* query = (const float*)d_in[0];
    const float* value = (const float*)d_in[1];
    const float* ref   = (const float*)d_in[2];
    const float* w_off = (const float*)d_in[3];
    const float* b_off = (const float*)d_in[4];
    const float* w_att = (const float*)d_in[5];
    const float* b_att = (const float*)d_in[6];
    const float* w_val = (const float*)d_in[7];
    const float* b_val = (const float*)d_in[8];
    float* out = (float*)d_out;

    static float* p_oa = nullptr;
    static __half* p_wth;
    static cudaStream_t s1;
    static cudaEvent_t e0, e1;
    if (!p_oa) {
        cudaGetSymbolAddress((void**)&p_oa, g_oa);
        cudaGetSymbolAddress((void**)&p_wth, g_wth);
        cudaFuncSetAttribute(gemm_mma, cudaFuncAttributeMaxDynamicSharedMemorySize, SMEM_TOTAL);
        cudaStreamCreateWithFlags(&s1, cudaStreamNonBlocking);
        cudaEventCreateWithFlags(&e0, cudaEventDisableTiming);
        cudaEventCreateWithFlags(&e1, cudaEventDisableTiming);
    }

    // fork: query chain on s1, value chain on main stream
    cudaEventRecord(e0, 0);
    cudaStreamWaitEvent(s1, e0, 0);

    wprepQ_kernel<<<196608 / 256, 256, 0, s1>>>(w_off, w_att, p_wth + 65536);
    {
        dim3 grid(6, (BB * QQ + 127) / 128);
        gemm_mma<<<grid, 256, SMEM_TOTAL, s1>>>(query, p_wth + 65536, b_off, b_att, 512,
                                                p_oa, BB * QQ, 768, 0);
    }

    wprepV_kernel<<<65536 / 256, 256>>>(w_val, p_wth);
    {
        dim3 grid(2, (BB * S_TOTAL + 127) / 128);
        gemm_mma<<<grid, 256, SMEM_TOTAL>>>(value, p_wth, b_val, b_val, 1 << 30,
                                            nullptr, BB * S_TOTAL, 256, 1);
    }

    // join
    cudaEventRecord(e1, s1);
    cudaStreamWaitEvent(0, e1, 0);

    sample_kernel<<<BB * QQ * NHH / 8, 256>>>(ref, out);
}